// round 15
// baseline (speedup 1.0000x reference)
#include <cuda_runtime.h>
#include <cuda_fp16.h>
#include <math.h>
#include <stdint.h>

#define B_ 4
#define S_ 2048
#define D_ 1024
#define H_ 16
#define DK 64
#define M_ (B_*S_)
#define NSTAGE 3
#define GSTB 32768u   // GEMM stage: Ah 16K | Wh 16K

// ---------------- scratch (device globals, allocation-free) ----------------
__device__ __align__(16) __half g_Ahi[M_*D_];
__device__ __align__(16) __half g_Wh[4*D_*D_];
__device__ __align__(16) __half g_Qh[M_*D_];
__device__ __align__(16) __half g_Kh[M_*D_];
__device__ __align__(16) __half g_Vth[M_*D_];
__device__ __align__(16) float2 g_rope[S_*32];

// ---------------- PTX helpers ----------------
__device__ __forceinline__ uint32_t s2u(const void* p){
    uint32_t a;
    asm("{ .reg .u64 t; cvta.to.shared.u64 t, %1; cvt.u32.u64 %0, t; }" : "=r"(a) : "l"(p));
    return a;
}
#define CP16(dst, src) \
    asm volatile("cp.async.cg.shared.global [%0], [%1], 16;" :: "r"(dst), "l"(src) : "memory")
#define CP_COMMIT() asm volatile("cp.async.commit_group;" ::: "memory")
#define CP_WAIT1()  asm volatile("cp.async.wait_group 1;" ::: "memory")

__device__ __forceinline__ void ldsm4(uint32_t r[4], uint32_t addr){
    asm volatile("ldmatrix.sync.aligned.m8n8.x4.shared.b16 {%0,%1,%2,%3}, [%4];"
                 : "=r"(r[0]), "=r"(r[1]), "=r"(r[2]), "=r"(r[3]) : "r"(addr));
}
__device__ __forceinline__ void mma16816(float c[4], const uint32_t a[4], const uint32_t b[2]){
    asm volatile("mma.sync.aligned.m16n8k16.row.col.f32.f16.f16.f32 "
                 "{%0,%1,%2,%3}, {%4,%5,%6,%7}, {%8,%9}, {%0,%1,%2,%3};"
                 : "+f"(c[0]), "+f"(c[1]), "+f"(c[2]), "+f"(c[3])
                 : "r"(a[0]), "r"(a[1]), "r"(a[2]), "r"(a[3]), "r"(b[0]), "r"(b[1]));
}
__device__ __forceinline__ void mma16816h(uint32_t c[2], const uint32_t a[4], const uint32_t b[2]){
    asm volatile("mma.sync.aligned.m16n8k16.row.col.f16.f16.f16.f16 "
                 "{%0,%1}, {%2,%3,%4,%5}, {%6,%7}, {%0,%1};"
                 : "+r"(c[0]), "+r"(c[1])
                 : "r"(a[0]), "r"(a[1]), "r"(a[2]), "r"(a[3]), "r"(b[0]), "r"(b[1]));
}
__device__ __forceinline__ uint32_t packo(float a, float b){
    __half2 h = __floats2half2_rn(a, b);
    return *(uint32_t*)&h;
}
__device__ __forceinline__ float2 unpk(uint32_t u){
    return __half22float2(*(__half2*)&u);
}

// ---------------------------------------------------------------------------
// converts + rope table
// ---------------------------------------------------------------------------
__global__ void convert_w(const float* __restrict__ W0, const float* __restrict__ W1,
                          const float* __restrict__ W2, const float* __restrict__ W3,
                          __half* __restrict__ hi)
{
    const float* X = (blockIdx.y==0) ? W0 : (blockIdx.y==1) ? W1 : (blockIdx.y==2) ? W2 : W3;
    const int idx = blockIdx.x * blockDim.x + threadIdx.x;
    const size_t off = (size_t)idx * 8;
    float4 v0 = *(const float4*)(X + off);
    float4 v1 = *(const float4*)(X + off + 4);
    uint32_t p[4] = { packo(v0.x,v0.y), packo(v0.z,v0.w), packo(v1.x,v1.y), packo(v1.z,v1.w) };
    *(uint4*)(hi + (size_t)blockIdx.y*D_*D_ + off) = make_uint4(p[0],p[1],p[2],p[3]);
}
__global__ void convert_x(const float* __restrict__ X, __half* __restrict__ hi)
{
    const int idx = blockIdx.x * blockDim.x + threadIdx.x;
    const size_t off = (size_t)idx * 8;
    float4 v0 = *(const float4*)(X + off);
    float4 v1 = *(const float4*)(X + off + 4);
    uint32_t p[4] = { packo(v0.x,v0.y), packo(v0.z,v0.w), packo(v1.x,v1.y), packo(v1.z,v1.w) };
    *(uint4*)(hi + off) = make_uint4(p[0],p[1],p[2],p[3]);
}
__global__ void fill_rope(float2* __restrict__ T)
{
    const int idx = blockIdx.x * blockDim.x + threadIdx.x;
    const int d2 = idx & 31;
    const int s  = idx >> 5;
    const float freq = exp2f(-(float)d2 * (13.287712379549449f / 32.0f));
    float sn, cs;
    sincosf((float)s * freq, &sn, &cs);
    T[idx] = make_float2(cs, sn);
}

// ---------------- GEMM tile loads (128 threads, 16KB tiles) ----------------
__device__ __forceinline__ void load_tile16(uint32_t sdst, const __half* src, int kt, int tid){
    #pragma unroll
    for (int j = 0; j < 8; j++) {
        const int q = tid + j*128;
        const int r = q >> 3, c = q & 7;
        CP16(sdst + (uint32_t)(r*128 + ((c ^ (r & 7))*16)), src + (size_t)r*D_ + kt*64 + c*8);
    }
}

#define GEMM_PIPE_HEAD(gA, gW)                                                 \
    _Pragma("unroll")                                                          \
    for (int p = 0; p < 2; p++) {                                              \
        const uint32_t st = sbase + p*GSTB;                                    \
        load_tile16(st, gA, p, tid);                                           \
        load_tile16(st + 16384, gW, p, tid);                                   \
        CP_COMMIT();                                                           \
    }

#define GEMM_PIPE_STEP(gA, gW)                                                 \
        CP_WAIT1();                                                            \
        __syncthreads();                                                       \
        if (i + 2 < NT) {                                                      \
            const uint32_t st = sbase + ((i+2)%NSTAGE)*GSTB;                   \
            load_tile16(st, gA, i+2, tid);                                     \
            load_tile16(st + 16384, gW, i+2, tid);                             \
        }                                                                      \
        CP_COMMIT();                                                           \
        const uint32_t sA = sbase + (i%NSTAGE)*GSTB;

#define GEMM_LOAD_FRAGS                                                        \
            uint32_t ah[4][4];                                                 \
            _Pragma("unroll")                                                  \
            for (int mt = 0; mt < 4; mt++) {                                   \
                const int row = wm*64 + mt*16 + (g & 1)*8 + l;                 \
                const int ch  = ks*2 + (g >> 1);                               \
                ldsm4(ah[mt], sA + (uint32_t)(row*128 + ((ch ^ (row & 7))*16))); \
            }                                                                  \
            uint32_t bh2[8][2];                                                \
            _Pragma("unroll")                                                  \
            for (int half = 0; half < 4; half++) {                             \
                const int row = wn*64 + half*16 + (g >> 1)*8 + l;              \
                const int ch  = ks*2 + (g & 1);                                \
                uint32_t t[4];                                                 \
                ldsm4(t, sA + 16384u + (uint32_t)(row*128 + ((ch ^ (row & 7))*16))); \
                bh2[2*half][0]=t[0]; bh2[2*half][1]=t[1];                      \
                bh2[2*half+1][0]=t[2]; bh2[2*half+1][1]=t[3];                  \
            }

// ---------------------------------------------------------------------------
// Q/K projection GEMM: fp16 accum, fused RoPE epilogue.
// ---------------------------------------------------------------------------
__global__ __launch_bounds__(128, 2) void gemm_qk(
    const __half* __restrict__ Ahi, const __half* __restrict__ Wh,
    const float2* __restrict__ rope,
    __half* __restrict__ Qh, __half* __restrict__ Kh)
{
    extern __shared__ __align__(128) char dsm[];
    const uint32_t sbase = s2u(dsm);
    const int tid  = threadIdx.x;
    const int lane = tid & 31;
    const int wid  = tid >> 5;
    const int wm   = wid & 1;
    const int wn   = wid >> 1;
    const int g    = lane >> 3, l = lane & 7;

    const int nb = blockIdx.x;
    const int mb = blockIdx.y;
    const int z  = blockIdx.z;

    const __half* gA = Ahi + (size_t)(mb*128) * D_;
    const __half* gW = Wh + (size_t)z*D_*D_ + (size_t)(nb*128) * D_;

    uint32_t acc16[4][8][2] = {};
    GEMM_PIPE_HEAD(gA, gW)
    constexpr int NT = D_/64;
    for (int i = 0; i < NT; i++) {
        GEMM_PIPE_STEP(gA, gW)
        #pragma unroll
        for (int ks = 0; ks < 4; ks++) {
            GEMM_LOAD_FRAGS
            #pragma unroll
            for (int mt = 0; mt < 4; mt++)
                #pragma unroll
                for (int nt = 0; nt < 8; nt++)
                    mma16816h(acc16[mt][nt], ah[mt], bh2[nt]);
        }
    }

    #pragma unroll
    for (int mt = 0; mt < 4; mt++) {
        #pragma unroll
        for (int half = 0; half < 2; half++) {
            const int m = mb*128 + wm*64 + mt*16 + (lane >> 2) + half*8;
            const int b = m >> 11, sq = m & (S_-1);
            #pragma unroll
            for (int nt = 0; nt < 8; nt++) {
                const int n = nb*128 + wn*64 + nt*8 + (lane & 3)*2;
                const int h = n >> 6, d = n & 63;
                const size_t bh_ = (size_t)(b*H_ + h);
                float2 v = unpk(acc16[mt][nt][half]);
                const float2 t = __ldg(rope + (sq << 5) + (d >> 1));
                float r0 = t.x*v.x - t.y*v.y;
                float r1 = t.y*v.x + t.x*v.y;
                if (z == 0) { r0 *= 0.125f; r1 *= 0.125f; }
                __half* dst = (z == 0 ? Qh : Kh) + (bh_*S_ + sq)*DK + d;
                *(uint32_t*)dst = packo(r0, r1);
            }
        }
    }
}

// ---------------------------------------------------------------------------
// V projection GEMM: fp32 accum, fused V^T epilogue.
// ---------------------------------------------------------------------------
__global__ __launch_bounds__(128, 2) void gemm_v(
    const __half* __restrict__ Ahi, const __half* __restrict__ Wh,
    __half* __restrict__ Vth)
{
    extern __shared__ __align__(128) char dsm[];
    const uint32_t sbase = s2u(dsm);
    const int tid  = threadIdx.x;
    const int lane = tid & 31;
    const int wid  = tid >> 5;
    const int wm   = wid & 1;
    const int wn   = wid >> 1;
    const int g    = lane >> 3, l = lane & 7;

    const int nb = blockIdx.x;
    const int mb = blockIdx.y;

    const __half* gA = Ahi + (size_t)(mb*128) * D_;
    const __half* gW = Wh + (size_t)2*D_*D_ + (size_t)(nb*128) * D_;

    float acc[4][8][4] = {};
    GEMM_PIPE_HEAD(gA, gW)
    constexpr int NT = D_/64;
    for (int i = 0; i < NT; i++) {
        GEMM_PIPE_STEP(gA, gW)
        #pragma unroll
        for (int ks = 0; ks < 4; ks++) {
            GEMM_LOAD_FRAGS
            #pragma unroll
            for (int mt = 0; mt < 4; mt++)
                #pragma unroll
                for (int nt = 0; nt < 8; nt++)
                    mma16816(acc[mt][nt], ah[mt], bh2[nt]);
        }
    }

    #pragma unroll
    for (int mt = 0; mt < 4; mt++) {
        #pragma unroll
        for (int half = 0; half < 2; half++) {
            const int m = mb*128 + wm*64 + mt*16 + (lane >> 2) + half*8;
            const int b = m >> 11, sq = m & (S_-1);
            #pragma unroll
            for (int nt = 0; nt < 8; nt++) {
                const int n = nb*128 + wn*64 + nt*8 + (lane & 3)*2;
                const int h = n >> 6, d = n & 63;
                const size_t bh_ = (size_t)(b*H_ + h);
                __half* dst = Vth + (bh_*DK + d)*S_ + sq;
                dst[0]  = __float2half(acc[mt][nt][2*half]);
                dst[S_] = __float2half(acc[mt][nt][2*half+1]);
            }
        }
    }
}

// ---------------------------------------------------------------------------
// Output projection GEMM: fp32 accum, fp32 out.
// ---------------------------------------------------------------------------
__global__ __launch_bounds__(128, 2) void gemm_out(
    const __half* __restrict__ Ahi, const __half* __restrict__ Wh,
    float* __restrict__ O)
{
    extern __shared__ __align__(128) char dsm[];
    const uint32_t sbase = s2u(dsm);
    const int tid  = threadIdx.x;
    const int lane = tid & 31;
    const int wid  = tid >> 5;
    const int wm   = wid & 1;
    const int wn   = wid >> 1;
    const int g    = lane >> 3, l = lane & 7;

    const int nb = blockIdx.x;
    const int mb = blockIdx.y;

    const __half* gA = Ahi + (size_t)(mb*128) * D_;
    const __half* gW = Wh + (size_t)3*D_*D_ + (size_t)(nb*128) * D_;

    float acc[4][8][4] = {};
    GEMM_PIPE_HEAD(gA, gW)
    constexpr int NT = D_/64;
    for (int i = 0; i < NT; i++) {
        GEMM_PIPE_STEP(gA, gW)
        #pragma unroll
        for (int ks = 0; ks < 4; ks++) {
            GEMM_LOAD_FRAGS
            #pragma unroll
            for (int mt = 0; mt < 4; mt++)
                #pragma unroll
                for (int nt = 0; nt < 8; nt++)
                    mma16816(acc[mt][nt], ah[mt], bh2[nt]);
        }
    }

    #pragma unroll
    for (int mt = 0; mt < 4; mt++) {
        #pragma unroll
        for (int nt = 0; nt < 8; nt++) {
            const int m0 = mb*128 + wm*64 + mt*16 + (lane >> 2);
            const int n  = nb*128 + wn*64 + nt*8 + (lane & 3)*2;
            #pragma unroll
            for (int half = 0; half < 2; half++) {
                const int m = m0 + half*8;
                *(float2*)(O + (size_t)m*D_ + n) =
                    make_float2(acc[mt][nt][2*half], acc[mt][nt][2*half+1]);
            }
        }
    }
}

// ---------------------------------------------------------------------------
// HMMA causal flash attention, static-max softmax.
// CTA = 128 q rows, 128 threads: 4 warps x 32 rows (2 m16 tiles/warp) ->
// K/V ldsm replication per q-row halved vs round-12. 2 CTAs/SM, 255-reg cap.
// smem: Q 16K | 3 x (K 8K | V 8K) = 64K. Single sync per tile; masked-out
// warps skip compute.
// ---------------------------------------------------------------------------
#define FA_STAGE 16384
__global__ __launch_bounds__(128, 2) void flash_mma(
    const __half* __restrict__ Qh, const __half* __restrict__ Kh,
    const __half* __restrict__ Vth, __half* __restrict__ Ohi)
{
    extern __shared__ __align__(128) char dsm[];
    const uint32_t sQ = s2u(dsm);
    const uint32_t sStg = sQ + 16384;

    const int tid  = threadIdx.x;
    const int lane = tid & 31;
    const int w    = tid >> 5;          // 0..3
    const int g    = lane >> 3, l = lane & 7;

    const int qt = (gridDim.x - 1) - blockIdx.x;
    const int bh = blockIdx.y;
    const int nkt = 2*qt + 2;

    const __half* gQh = Qh + ((size_t)bh*S_ + qt*128)*DK;
    const __half* gKh = Kh + (size_t)bh*S_*DK;
    const __half* gVh = Vth + (size_t)bh*DK*S_;

    // Q: 128x64 fp16 = 16KB, 8 CP16/thread at 128 threads
    {
        #pragma unroll
        for (int j = 0; j < 8; j++) {
            const int q = tid + j*128;
            const int r = q >> 3, c = q & 7;
            CP16(sQ + (uint32_t)(r*128 + ((c ^ (r & 7))*16)), gQh + (size_t)r*DK + c*8);
        }
    }
    #define LOAD_STAGE(buf, kt) do {                                           \
        const uint32_t bse = sStg + (buf)*FA_STAGE;                            \
        _Pragma("unroll")                                                      \
        for (int j = 0; j < 4; j++) {                                          \
            const int q = tid + j*128;                                         \
            const int r = q >> 3, c = q & 7;                                   \
            const uint32_t d = (uint32_t)(r*128 + ((c ^ (r & 7))*16));         \
            CP16(bse + d,        gKh + (size_t)((kt)*64 + r)*DK + c*8);        \
            CP16(bse + 8192 + d, gVh + (size_t)r*S_ + (kt)*64 + c*8);          \
        }                                                                      \
    } while (0)

    LOAD_STAGE(0, 0);
    CP_COMMIT();
    LOAD_STAGE(1, 1);
    CP_COMMIT();

    uint32_t qhf[2][4][4];           // [mt][ks]
    float oacc[2][8][4] = {};
    float lsum[2][2] = {};
    const int rowBase = qt*128 + w*32;

    for (int kt = 0; kt < nkt; kt++) {
        CP_WAIT1();
        __syncthreads();

        if (kt == 0) {
            #pragma unroll
            for (int mt = 0; mt < 2; mt++)
                #pragma unroll
                for (int ks = 0; ks < 4; ks++) {
                    const int row = w*32 + mt*16 + (g & 1)*8 + l;
                    const int ch  = ks*2 + (g >> 1);
                    ldsm4(qhf[mt][ks], sQ + (uint32_t)(row*128 + ((ch ^ (row & 7))*16)));
                }
        }
        if (kt + 2 < nkt) LOAD_STAGE((kt+2)%3, kt+2);
        CP_COMMIT();

        // Fully-masked tile for this warp?
        if (kt*64 > rowBase + 31) continue;

        const uint32_t bse = sStg + (kt%3)*FA_STAGE;

        // ---- S = Q K^T (fp16 accum), both m-tiles share each K fragment
        uint32_t sacc16[2][8][2] = {};
        #pragma unroll
        for (int ks = 0; ks < 4; ks++) {
            uint32_t kh4[4][4];
            #pragma unroll
            for (int p = 0; p < 4; p++) {
                const int row = p*16 + (g >> 1)*8 + l;
                const int ch  = ks*2 + (g & 1);
                ldsm4(kh4[p], bse + (uint32_t)(row*128 + ((ch ^ (row & 7))*16)));
            }
            #pragma unroll
            for (int p = 0; p < 4; p++) {
                uint32_t b0[2] = {kh4[p][0], kh4[p][1]}, b1[2] = {kh4[p][2], kh4[p][3]};
                #pragma unroll
                for (int mt = 0; mt < 2; mt++) {
                    mma16816h(sacc16[mt][2*p],   qhf[mt][ks], b0);
                    mma16816h(sacc16[mt][2*p+1], qhf[mt][ks], b1);
                }
            }
        }

        // ---- unpack + mask + exp (static max 0) + sums; repack P in place
        const bool diag = (kt*64 + 63 > rowBase);
        #pragma unroll
        for (int mt = 0; mt < 2; mt++) {
            const int r0 = rowBase + mt*16 + (lane >> 2);
            float s0 = 0.f, s1 = 0.f;
            #pragma unroll
            for (int nb = 0; nb < 8; nb++) {
                float2 v01 = unpk(sacc16[mt][nb][0]);
                float2 v23 = unpk(sacc16[mt][nb][1]);
                if (diag) {
                    const int col = kt*64 + nb*8 + (lane & 3)*2;
                    if (col   > r0)   v01.x = -1e30f;
                    if (col+1 > r0)   v01.y = -1e30f;
                    if (col   > r0+8) v23.x = -1e30f;
                    if (col+1 > r0+8) v23.y = -1e30f;
                }
                v01.x = __expf(v01.x); v01.y = __expf(v01.y);
                v23.x = __expf(v23.x); v23.y = __expf(v23.y);
                s0 += v01.x + v01.y;
                s1 += v23.x + v23.y;
                sacc16[mt][nb][0] = packo(v01.x, v01.y);
                sacc16[mt][nb][1] = packo(v23.x, v23.y);
            }
            s0 += __shfl_xor_sync(0xffffffffu, s0, 1);
            s0 += __shfl_xor_sync(0xffffffffu, s0, 2);
            s1 += __shfl_xor_sync(0xffffffffu, s1, 1);
            s1 += __shfl_xor_sync(0xffffffffu, s1, 2);
            lsum[mt][0] += s0;
            lsum[mt][1] += s1;
        }

        // ---- PV (fp16 accum per tile), V fragments shared across m-tiles
        uint32_t pv16[2][8][2] = {};
        #pragma unroll
        for (int kc = 0; kc < 4; kc++) {
            uint32_t vh4[4][4];
            #pragma unroll
            for (int p = 0; p < 4; p++) {
                const int row = p*16 + (g >> 1)*8 + l;
                const int ch  = kc*2 + (g & 1);
                ldsm4(vh4[p], bse + 8192u + (uint32_t)(row*128 + ((ch ^ (row & 7))*16)));
            }
            #pragma unroll
            for (int mt = 0; mt < 2; mt++) {
                uint32_t aH[4] = {sacc16[mt][2*kc][0], sacc16[mt][2*kc][1],
                                  sacc16[mt][2*kc+1][0], sacc16[mt][2*kc+1][1]};
                #pragma unroll
                for (int p = 0; p < 4; p++) {
                    uint32_t b0[2] = {vh4[p][0], vh4[p][1]}, b1[2] = {vh4[p][2], vh4[p][3]};
                    mma16816h(pv16[mt][2*p],   aH, b0);
                    mma16816h(pv16[mt][2*p+1], aH, b1);
                }
            }
        }
        #pragma unroll
        for (int mt = 0; mt < 2; mt++)
            #pragma unroll
            for (int nb = 0; nb < 8; nb++) {
                float2 a = unpk(pv16[mt][nb][0]);
                float2 b = unpk(pv16[mt][nb][1]);
                oacc[mt][nb][0] += a.x; oacc[mt][nb][1] += a.y;
                oacc[mt][nb][2] += b.x; oacc[mt][nb][3] += b.y;
            }
    }

    // ---- epilogue
    const int b = bh >> 4;
    const int h = bh & 15;
    #pragma unroll
    for (int mt = 0; mt < 2; mt++) {
        const float i0 = 1.f / lsum[mt][0];
        const float i1 = 1.f / lsum[mt][1];
        const int r0 = rowBase + mt*16 + (lane >> 2);
        #pragma unroll
        for (int nb = 0; nb < 8; nb++) {
            const int col = h*64 + nb*8 + (lane & 3)*2;
            size_t o = ((size_t)(b*S_ + r0))*D_ + col;
            *(uint32_t*)(Ohi + o) = packo(oacc[mt][nb][0]*i0, oacc[mt][nb][1]*i0);
            o = ((size_t)(b*S_ + r0 + 8))*D_ + col;
            *(uint32_t*)(Ohi + o) = packo(oacc[mt][nb][2]*i1, oacc[mt][nb][3]*i1);
        }
    }
}

// ---------------------------------------------------------------------------
extern "C" void kernel_launch(void* const* d_in, const int* in_sizes, int n_in,
                              void* d_out, int out_size)
{
    const float* x  = (const float*)d_in[0];
    const float* WQ = (const float*)d_in[1];
    const float* WK = (const float*)d_in[2];
    const float* WV = (const float*)d_in[3];
    const float* WO = (const float*)d_in[4];
    float* out = (float*)d_out;

    __half *gAhi, *gWh, *gQh, *gKh, *gVth;
    float2* gRope;
    cudaGetSymbolAddress((void**)&gAhi, g_Ahi);
    cudaGetSymbolAddress((void**)&gWh, g_Wh);
    cudaGetSymbolAddress((void**)&gQh, g_Qh);
    cudaGetSymbolAddress((void**)&gKh, g_Kh);
    cudaGetSymbolAddress((void**)&gVth, g_Vth);
    cudaGetSymbolAddress((void**)&gRope, g_rope);

    const int gemm_smem = NSTAGE*GSTB;        // 98304 -> 2 CTAs/SM
    cudaFuncSetAttribute((const void*)gemm_qk,
                         cudaFuncAttributeMaxDynamicSharedMemorySize, gemm_smem);
    cudaFuncSetAttribute((const void*)gemm_v,
                         cudaFuncAttributeMaxDynamicSharedMemorySize, gemm_smem);
    cudaFuncSetAttribute((const void*)gemm_out,
                         cudaFuncAttributeMaxDynamicSharedMemorySize, gemm_smem);
    const int fa_smem = 16384 + 3*FA_STAGE;   // 65536
    cudaFuncSetAttribute((const void*)flash_mma,
                         cudaFuncAttributeMaxDynamicSharedMemorySize, fa_smem);

    // 0) weights + x -> fp16; rope table
    convert_w<<<dim3(512, 4), 256>>>(WQ, WK, WV, WO, gWh);
    convert_x<<<4096, 256>>>(x, gAhi);
    fill_rope<<<(S_*32)/256, 256>>>(gRope);

    // 1) projections
    gemm_qk<<<dim3(8, 64, 2), 128, gemm_smem>>>(gAhi, gWh, gRope, gQh, gKh);
    gemm_v<<<dim3(8, 64), 128, gemm_smem>>>(gAhi, gWh, gVth);

    // 2) flash attention (128 q-rows/CTA, 4 warps x 32 rows) -> fp16 [B,S,D]
    flash_mma<<<dim3(S_/128, B_*H_), 128, fa_smem>>>(gQh, gKh, gVth, gAhi);

    // 3) output projection -> fp32
    gemm_out<<<dim3(8, 64), 128, gemm_smem>>>(gAhi, gWh, out);
}

// round 16
// speedup vs baseline: 1.0528x; 1.0528x over previous
#include <cuda_runtime.h>
#include <cuda_fp16.h>
#include <math.h>
#include <stdint.h>

#define B_ 4
#define S_ 2048
#define D_ 1024
#define H_ 16
#define DK 64
#define M_ (B_*S_)
#define NSTAGE 3
#define GSTB 32768u   // GEMM stage: Ah 16K | Wh 16K

// ---------------- scratch (device globals, allocation-free) ----------------
__device__ __align__(16) __half g_Ahi[M_*D_];
__device__ __align__(16) __half g_Wh[4*D_*D_];
__device__ __align__(16) __half g_Qh[M_*D_];
__device__ __align__(16) __half g_Kh[M_*D_];
__device__ __align__(16) __half g_Vth[M_*D_];
__device__ __align__(16) float2 g_rope[S_*32];

// ---------------- PTX helpers ----------------
__device__ __forceinline__ uint32_t s2u(const void* p){
    uint32_t a;
    asm("{ .reg .u64 t; cvta.to.shared.u64 t, %1; cvt.u32.u64 %0, t; }" : "=r"(a) : "l"(p));
    return a;
}
#define CP16(dst, src) \
    asm volatile("cp.async.cg.shared.global [%0], [%1], 16;" :: "r"(dst), "l"(src) : "memory")
#define CP_COMMIT() asm volatile("cp.async.commit_group;" ::: "memory")
#define CP_WAIT1()  asm volatile("cp.async.wait_group 1;" ::: "memory")

__device__ __forceinline__ void ldsm4(uint32_t r[4], uint32_t addr){
    asm volatile("ldmatrix.sync.aligned.m8n8.x4.shared.b16 {%0,%1,%2,%3}, [%4];"
                 : "=r"(r[0]), "=r"(r[1]), "=r"(r[2]), "=r"(r[3]) : "r"(addr));
}
__device__ __forceinline__ void mma16816(float c[4], const uint32_t a[4], const uint32_t b[2]){
    asm volatile("mma.sync.aligned.m16n8k16.row.col.f32.f16.f16.f32 "
                 "{%0,%1,%2,%3}, {%4,%5,%6,%7}, {%8,%9}, {%0,%1,%2,%3};"
                 : "+f"(c[0]), "+f"(c[1]), "+f"(c[2]), "+f"(c[3])
                 : "r"(a[0]), "r"(a[1]), "r"(a[2]), "r"(a[3]), "r"(b[0]), "r"(b[1]));
}
__device__ __forceinline__ void mma16816h(uint32_t c[2], const uint32_t a[4], const uint32_t b[2]){
    asm volatile("mma.sync.aligned.m16n8k16.row.col.f16.f16.f16.f16 "
                 "{%0,%1}, {%2,%3,%4,%5}, {%6,%7}, {%0,%1};"
                 : "+r"(c[0]), "+r"(c[1])
                 : "r"(a[0]), "r"(a[1]), "r"(a[2]), "r"(a[3]), "r"(b[0]), "r"(b[1]));
}
__device__ __forceinline__ uint32_t packo(float a, float b){
    __half2 h = __floats2half2_rn(a, b);
    return *(uint32_t*)&h;
}
__device__ __forceinline__ float2 unpk(uint32_t u){
    return __half22float2(*(__half2*)&u);
}

// ---------------------------------------------------------------------------
// Merged prep kernel: one launch does x->fp16, W0..3->fp16, rope table.
// blocks [0,4096): x | [4096,6144): W | [6144,6400): rope
// ---------------------------------------------------------------------------
__global__ void prep_all(const float* __restrict__ X,
                         const float* __restrict__ W0, const float* __restrict__ W1,
                         const float* __restrict__ W2, const float* __restrict__ W3,
                         __half* __restrict__ Ahi, __half* __restrict__ Wh,
                         float2* __restrict__ T)
{
    const int blk = blockIdx.x;
    if (blk < 4096) {
        const int idx = blk * 256 + threadIdx.x;
        const size_t off = (size_t)idx * 8;
        float4 v0 = *(const float4*)(X + off);
        float4 v1 = *(const float4*)(X + off + 4);
        uint32_t p[4] = { packo(v0.x,v0.y), packo(v0.z,v0.w), packo(v1.x,v1.y), packo(v1.z,v1.w) };
        *(uint4*)(Ahi + off) = make_uint4(p[0],p[1],p[2],p[3]);
    } else if (blk < 6144) {
        const int wb = blk - 4096;        // 0..2047, 512 blocks per weight
        const int wz = wb >> 9;
        const float* W = (wz==0) ? W0 : (wz==1) ? W1 : (wz==2) ? W2 : W3;
        const int idx = (wb & 511) * 256 + threadIdx.x;
        const size_t off = (size_t)idx * 8;
        float4 v0 = *(const float4*)(W + off);
        float4 v1 = *(const float4*)(W + off + 4);
        uint32_t p[4] = { packo(v0.x,v0.y), packo(v0.z,v0.w), packo(v1.x,v1.y), packo(v1.z,v1.w) };
        *(uint4*)(Wh + (size_t)wz*D_*D_ + off) = make_uint4(p[0],p[1],p[2],p[3]);
    } else {
        const int idx = (blk - 6144) * 256 + threadIdx.x;   // s*32 + d2
        const int d2 = idx & 31;
        const int s  = idx >> 5;
        const float freq = exp2f(-(float)d2 * (13.287712379549449f / 32.0f));
        float sn, cs;
        sincosf((float)s * freq, &sn, &cs);
        T[idx] = make_float2(cs, sn);
    }
}

// ---------------- GEMM tile loads (128 threads, 16KB tiles) ----------------
__device__ __forceinline__ void load_tile16(uint32_t sdst, const __half* src, int kt, int tid){
    #pragma unroll
    for (int j = 0; j < 8; j++) {
        const int q = tid + j*128;
        const int r = q >> 3, c = q & 7;
        CP16(sdst + (uint32_t)(r*128 + ((c ^ (r & 7))*16)), src + (size_t)r*D_ + kt*64 + c*8);
    }
}

#define GEMM_PIPE_HEAD(gA, gW)                                                 \
    _Pragma("unroll")                                                          \
    for (int p = 0; p < 2; p++) {                                              \
        const uint32_t st = sbase + p*GSTB;                                    \
        load_tile16(st, gA, p, tid);                                           \
        load_tile16(st + 16384, gW, p, tid);                                   \
        CP_COMMIT();                                                           \
    }

#define GEMM_PIPE_STEP(gA, gW)                                                 \
        CP_WAIT1();                                                            \
        __syncthreads();                                                       \
        if (i + 2 < NT) {                                                      \
            const uint32_t st = sbase + ((i+2)%NSTAGE)*GSTB;                   \
            load_tile16(st, gA, i+2, tid);                                     \
            load_tile16(st + 16384, gW, i+2, tid);                             \
        }                                                                      \
        CP_COMMIT();                                                           \
        const uint32_t sA = sbase + (i%NSTAGE)*GSTB;

#define GEMM_LOAD_FRAGS                                                        \
            uint32_t ah[4][4];                                                 \
            _Pragma("unroll")                                                  \
            for (int mt = 0; mt < 4; mt++) {                                   \
                const int row = wm*64 + mt*16 + (g & 1)*8 + l;                 \
                const int ch  = ks*2 + (g >> 1);                               \
                ldsm4(ah[mt], sA + (uint32_t)(row*128 + ((ch ^ (row & 7))*16))); \
            }                                                                  \
            uint32_t bh2[8][2];                                                \
            _Pragma("unroll")                                                  \
            for (int half = 0; half < 4; half++) {                             \
                const int row = wn*64 + half*16 + (g >> 1)*8 + l;              \
                const int ch  = ks*2 + (g & 1);                                \
                uint32_t t[4];                                                 \
                ldsm4(t, sA + 16384u + (uint32_t)(row*128 + ((ch ^ (row & 7))*16))); \
                bh2[2*half][0]=t[0]; bh2[2*half][1]=t[1];                      \
                bh2[2*half+1][0]=t[2]; bh2[2*half+1][1]=t[3];                  \
            }

// ---------------------------------------------------------------------------
// Merged Q/K/V projection GEMM. z=0: Q (fp16 accum, rope, /8). z=1: K (fp16
// accum, rope). z=2: V (fp32 accum, V^T epilogue). Whole-CTA branch.
// ---------------------------------------------------------------------------
__global__ __launch_bounds__(128, 2) void gemm_qkv(
    const __half* __restrict__ Ahi, const __half* __restrict__ Wh,
    const float2* __restrict__ rope,
    __half* __restrict__ Qh, __half* __restrict__ Kh, __half* __restrict__ Vth)
{
    extern __shared__ __align__(128) char dsm[];
    const uint32_t sbase = s2u(dsm);
    const int tid  = threadIdx.x;
    const int lane = tid & 31;
    const int wid  = tid >> 5;
    const int wm   = wid & 1;
    const int wn   = wid >> 1;
    const int g    = lane >> 3, l = lane & 7;

    const int nb = blockIdx.x;
    const int mb = blockIdx.y;
    const int z  = blockIdx.z;

    const __half* gA = Ahi + (size_t)(mb*128) * D_;
    const __half* gW = Wh + (size_t)z*D_*D_ + (size_t)(nb*128) * D_;
    constexpr int NT = D_/64;

    if (z < 2) {
        // ---- fp16-accum path (Q/K), fused RoPE epilogue
        uint32_t acc16[4][8][2] = {};
        GEMM_PIPE_HEAD(gA, gW)
        for (int i = 0; i < NT; i++) {
            GEMM_PIPE_STEP(gA, gW)
            #pragma unroll
            for (int ks = 0; ks < 4; ks++) {
                GEMM_LOAD_FRAGS
                #pragma unroll
                for (int mt = 0; mt < 4; mt++)
                    #pragma unroll
                    for (int nt = 0; nt < 8; nt++)
                        mma16816h(acc16[mt][nt], ah[mt], bh2[nt]);
            }
        }
        #pragma unroll
        for (int mt = 0; mt < 4; mt++) {
            #pragma unroll
            for (int half = 0; half < 2; half++) {
                const int m = mb*128 + wm*64 + mt*16 + (lane >> 2) + half*8;
                const int b = m >> 11, sq = m & (S_-1);
                #pragma unroll
                for (int nt = 0; nt < 8; nt++) {
                    const int n = nb*128 + wn*64 + nt*8 + (lane & 3)*2;
                    const int h = n >> 6, d = n & 63;
                    const size_t bh_ = (size_t)(b*H_ + h);
                    float2 v = unpk(acc16[mt][nt][half]);
                    const float2 t = __ldg(rope + (sq << 5) + (d >> 1));
                    float r0 = t.x*v.x - t.y*v.y;
                    float r1 = t.y*v.x + t.x*v.y;
                    if (z == 0) { r0 *= 0.125f; r1 *= 0.125f; }
                    __half* dst = (z == 0 ? Qh : Kh) + (bh_*S_ + sq)*DK + d;
                    *(uint32_t*)dst = packo(r0, r1);
                }
            }
        }
    } else {
        // ---- fp32-accum path (V), fused V^T epilogue
        float acc[4][8][4] = {};
        GEMM_PIPE_HEAD(gA, gW)
        for (int i = 0; i < NT; i++) {
            GEMM_PIPE_STEP(gA, gW)
            #pragma unroll
            for (int ks = 0; ks < 4; ks++) {
                GEMM_LOAD_FRAGS
                #pragma unroll
                for (int mt = 0; mt < 4; mt++)
                    #pragma unroll
                    for (int nt = 0; nt < 8; nt++)
                        mma16816(acc[mt][nt], ah[mt], bh2[nt]);
            }
        }
        #pragma unroll
        for (int mt = 0; mt < 4; mt++) {
            #pragma unroll
            for (int half = 0; half < 2; half++) {
                const int m = mb*128 + wm*64 + mt*16 + (lane >> 2) + half*8;
                const int b = m >> 11, sq = m & (S_-1);
                #pragma unroll
                for (int nt = 0; nt < 8; nt++) {
                    const int n = nb*128 + wn*64 + nt*8 + (lane & 3)*2;
                    const int h = n >> 6, d = n & 63;
                    const size_t bh_ = (size_t)(b*H_ + h);
                    __half* dst = Vth + (bh_*DK + d)*S_ + sq;
                    dst[0]  = __float2half(acc[mt][nt][2*half]);
                    dst[S_] = __float2half(acc[mt][nt][2*half+1]);
                }
            }
        }
    }
}

// ---------------------------------------------------------------------------
// Output projection GEMM: fp32 accum, fp32 out.
// ---------------------------------------------------------------------------
__global__ __launch_bounds__(128, 2) void gemm_out(
    const __half* __restrict__ Ahi, const __half* __restrict__ Wh,
    float* __restrict__ O)
{
    extern __shared__ __align__(128) char dsm[];
    const uint32_t sbase = s2u(dsm);
    const int tid  = threadIdx.x;
    const int lane = tid & 31;
    const int wid  = tid >> 5;
    const int wm   = wid & 1;
    const int wn   = wid >> 1;
    const int g    = lane >> 3, l = lane & 7;

    const int nb = blockIdx.x;
    const int mb = blockIdx.y;

    const __half* gA = Ahi + (size_t)(mb*128) * D_;
    const __half* gW = Wh + (size_t)3*D_*D_ + (size_t)(nb*128) * D_;

    float acc[4][8][4] = {};
    GEMM_PIPE_HEAD(gA, gW)
    constexpr int NT = D_/64;
    for (int i = 0; i < NT; i++) {
        GEMM_PIPE_STEP(gA, gW)
        #pragma unroll
        for (int ks = 0; ks < 4; ks++) {
            GEMM_LOAD_FRAGS
            #pragma unroll
            for (int mt = 0; mt < 4; mt++)
                #pragma unroll
                for (int nt = 0; nt < 8; nt++)
                    mma16816(acc[mt][nt], ah[mt], bh2[nt]);
        }
    }

    #pragma unroll
    for (int mt = 0; mt < 4; mt++) {
        #pragma unroll
        for (int nt = 0; nt < 8; nt++) {
            const int m0 = mb*128 + wm*64 + mt*16 + (lane >> 2);
            const int n  = nb*128 + wn*64 + nt*8 + (lane & 3)*2;
            #pragma unroll
            for (int half = 0; half < 2; half++) {
                const int m = m0 + half*8;
                *(float2*)(O + (size_t)m*D_ + n) =
                    make_float2(acc[mt][nt][2*half], acc[mt][nt][2*half+1]);
            }
        }
    }
}

// ---------------------------------------------------------------------------
// HMMA causal flash attention (round-14 config: 128 q rows, 8 warps x 16 rows,
// 2 CTAs/SM, static-max softmax, single sync/tile, masked-warp skip).
// ---------------------------------------------------------------------------
#define FA_STAGE 16384
__global__ __launch_bounds__(256, 2) void flash_mma(
    const __half* __restrict__ Qh, const __half* __restrict__ Kh,
    const __half* __restrict__ Vth, __half* __restrict__ Ohi)
{
    extern __shared__ __align__(128) char dsm[];
    const uint32_t sQ = s2u(dsm);
    const uint32_t sStg = sQ + 16384;

    const int tid  = threadIdx.x;
    const int lane = tid & 31;
    const int w    = tid >> 5;
    const int g    = lane >> 3, l = lane & 7;

    const int qt = (gridDim.x - 1) - blockIdx.x;
    const int bh = blockIdx.y;
    const int nkt = 2*qt + 2;

    const __half* gQh = Qh + ((size_t)bh*S_ + qt*128)*DK;
    const __half* gKh = Kh + (size_t)bh*S_*DK;
    const __half* gVh = Vth + (size_t)bh*DK*S_;

    {
        #pragma unroll
        for (int j = 0; j < 4; j++) {
            const int q = tid + j*256;
            const int r = q >> 3, c = q & 7;
            CP16(sQ + (uint32_t)(r*128 + ((c ^ (r & 7))*16)), gQh + (size_t)r*DK + c*8);
        }
    }
    #define LOAD_STAGE(buf, kt) do {                                           \
        const uint32_t bse = sStg + (buf)*FA_STAGE;                            \
        _Pragma("unroll")                                                      \
        for (int j = 0; j < 2; j++) {                                          \
            const int q = tid + j*256;                                         \
            const int r = q >> 3, c = q & 7;                                   \
            const uint32_t d = (uint32_t)(r*128 + ((c ^ (r & 7))*16));         \
            CP16(bse + d,        gKh + (size_t)((kt)*64 + r)*DK + c*8);        \
            CP16(bse + 8192 + d, gVh + (size_t)r*S_ + (kt)*64 + c*8);          \
        }                                                                      \
    } while (0)

    LOAD_STAGE(0, 0);
    CP_COMMIT();
    LOAD_STAGE(1, 1);
    CP_COMMIT();

    uint32_t qhf[4][4];
    float oacc[8][4] = {};
    float l0 = 0.f, l1 = 0.f;
    const int rowBase = qt*128 + w*16;

    for (int kt = 0; kt < nkt; kt++) {
        CP_WAIT1();
        __syncthreads();

        if (kt == 0) {
            #pragma unroll
            for (int ks = 0; ks < 4; ks++) {
                const int row = w*16 + (g & 1)*8 + l;
                const int ch  = ks*2 + (g >> 1);
                ldsm4(qhf[ks], sQ + (uint32_t)(row*128 + ((ch ^ (row & 7))*16)));
            }
        }
        if (kt + 2 < nkt) LOAD_STAGE((kt+2)%3, kt+2);
        CP_COMMIT();

        if (kt*64 > rowBase + 15) continue;

        const uint32_t bse = sStg + (kt%3)*FA_STAGE;

        uint32_t sacc16[8][2] = {};
        #pragma unroll
        for (int ks = 0; ks < 4; ks++) {
            uint32_t kh4[4][4];
            #pragma unroll
            for (int p = 0; p < 4; p++) {
                const int row = p*16 + (g >> 1)*8 + l;
                const int ch  = ks*2 + (g & 1);
                ldsm4(kh4[p], bse + (uint32_t)(row*128 + ((ch ^ (row & 7))*16)));
            }
            #pragma unroll
            for (int p = 0; p < 4; p++) {
                uint32_t b0[2] = {kh4[p][0], kh4[p][1]}, b1[2] = {kh4[p][2], kh4[p][3]};
                mma16816h(sacc16[2*p],   qhf[ks], b0);
                mma16816h(sacc16[2*p+1], qhf[ks], b1);
            }
        }

        float sacc[8][4];
        const int row0 = rowBase + (lane >> 2);
        #pragma unroll
        for (int nb = 0; nb < 8; nb++) {
            float2 v01 = unpk(sacc16[nb][0]);
            float2 v23 = unpk(sacc16[nb][1]);
            sacc[nb][0] = v01.x; sacc[nb][1] = v01.y;
            sacc[nb][2] = v23.x; sacc[nb][3] = v23.y;
        }
        if (kt*64 + 63 > row0) {
            #pragma unroll
            for (int nb = 0; nb < 8; nb++) {
                const int col = kt*64 + nb*8 + (lane & 3)*2;
                if (col   > row0)   sacc[nb][0] = -1e30f;
                if (col+1 > row0)   sacc[nb][1] = -1e30f;
                if (col   > row0+8) sacc[nb][2] = -1e30f;
                if (col+1 > row0+8) sacc[nb][3] = -1e30f;
            }
        }

        float s0 = 0.f, s1 = 0.f;
        #pragma unroll
        for (int nb = 0; nb < 8; nb++) {
            sacc[nb][0] = __expf(sacc[nb][0]);
            sacc[nb][1] = __expf(sacc[nb][1]);
            sacc[nb][2] = __expf(sacc[nb][2]);
            sacc[nb][3] = __expf(sacc[nb][3]);
            s0 += sacc[nb][0] + sacc[nb][1];
            s1 += sacc[nb][2] + sacc[nb][3];
        }
        s0 += __shfl_xor_sync(0xffffffffu, s0, 1);
        s0 += __shfl_xor_sync(0xffffffffu, s0, 2);
        s1 += __shfl_xor_sync(0xffffffffu, s1, 1);
        s1 += __shfl_xor_sync(0xffffffffu, s1, 2);
        l0 += s0;
        l1 += s1;

        uint32_t p01[8], p23[8];
        #pragma unroll
        for (int nb = 0; nb < 8; nb++) {
            p01[nb] = packo(sacc[nb][0], sacc[nb][1]);
            p23[nb] = packo(sacc[nb][2], sacc[nb][3]);
        }

        uint32_t pv16[8][2] = {};
        #pragma unroll
        for (int kc = 0; kc < 4; kc++) {
            uint32_t vh4[4][4];
            #pragma unroll
            for (int p = 0; p < 4; p++) {
                const int row = p*16 + (g >> 1)*8 + l;
                const int ch  = kc*2 + (g & 1);
                ldsm4(vh4[p], bse + 8192u + (uint32_t)(row*128 + ((ch ^ (row & 7))*16)));
            }
            uint32_t aH[4] = {p01[2*kc], p23[2*kc], p01[2*kc+1], p23[2*kc+1]};
            #pragma unroll
            for (int p = 0; p < 4; p++) {
                uint32_t b0[2] = {vh4[p][0], vh4[p][1]}, b1[2] = {vh4[p][2], vh4[p][3]};
                mma16816h(pv16[2*p],   aH, b0);
                mma16816h(pv16[2*p+1], aH, b1);
            }
        }
        #pragma unroll
        for (int nb = 0; nb < 8; nb++) {
            float2 a = unpk(pv16[nb][0]);
            float2 b = unpk(pv16[nb][1]);
            oacc[nb][0] += a.x; oacc[nb][1] += a.y;
            oacc[nb][2] += b.x; oacc[nb][3] += b.y;
        }
    }

    const int b = bh >> 4;
    const int h = bh & 15;
    const float i0 = 1.f / l0;
    const float i1 = 1.f / l1;
    const int r0 = rowBase + (lane >> 2);
    #pragma unroll
    for (int nb = 0; nb < 8; nb++) {
        const int col = h*64 + nb*8 + (lane & 3)*2;
        size_t o = ((size_t)(b*S_ + r0))*D_ + col;
        *(uint32_t*)(Ohi + o) = packo(oacc[nb][0]*i0, oacc[nb][1]*i0);
        o = ((size_t)(b*S_ + r0 + 8))*D_ + col;
        *(uint32_t*)(Ohi + o) = packo(oacc[nb][2]*i1, oacc[nb][3]*i1);
    }
}

// ---------------------------------------------------------------------------
extern "C" void kernel_launch(void* const* d_in, const int* in_sizes, int n_in,
                              void* d_out, int out_size)
{
    const float* x  = (const float*)d_in[0];
    const float* WQ = (const float*)d_in[1];
    const float* WK = (const float*)d_in[2];
    const float* WV = (const float*)d_in[3];
    const float* WO = (const float*)d_in[4];
    float* out = (float*)d_out;

    __half *gAhi, *gWh, *gQh, *gKh, *gVth;
    float2* gRope;
    cudaGetSymbolAddress((void**)&gAhi, g_Ahi);
    cudaGetSymbolAddress((void**)&gWh, g_Wh);
    cudaGetSymbolAddress((void**)&gQh, g_Qh);
    cudaGetSymbolAddress((void**)&gKh, g_Kh);
    cudaGetSymbolAddress((void**)&gVth, g_Vth);
    cudaGetSymbolAddress((void**)&gRope, g_rope);

    const int gemm_smem = NSTAGE*GSTB;        // 98304 -> 2 CTAs/SM
    cudaFuncSetAttribute((const void*)gemm_qkv,
                         cudaFuncAttributeMaxDynamicSharedMemorySize, gemm_smem);
    cudaFuncSetAttribute((const void*)gemm_out,
                         cudaFuncAttributeMaxDynamicSharedMemorySize, gemm_smem);
    const int fa_smem = 16384 + 3*FA_STAGE;   // 65536
    cudaFuncSetAttribute((const void*)flash_mma,
                         cudaFuncAttributeMaxDynamicSharedMemorySize, fa_smem);

    // 0) single prep launch: x + W0..3 -> fp16, rope table
    prep_all<<<6400, 256>>>(x, WQ, WK, WV, WO, gAhi, gWh, gRope);

    // 1) single QKV projection launch (z=0 Q, z=1 K, z=2 V)
    gemm_qkv<<<dim3(8, 64, 3), 128, gemm_smem>>>(gAhi, gWh, gRope, gQh, gKh, gVth);

    // 2) flash attention -> fp16 merged [B,S,D]
    flash_mma<<<dim3(S_/128, B_*H_), 256, fa_smem>>>(gQh, gKh, gVth, gAhi);

    // 3) output projection -> fp32
    gemm_out<<<dim3(8, 64), 128, gemm_smem>>>(gAhi, gWh, out);
}